// round 1
// baseline (speedup 1.0000x reference)
#include <cuda_runtime.h>
#include <math.h>

#define BN_EPS 1e-5f

// ---------------- scratch (device globals; no allocation allowed) ----------------
__device__ float g_h1[4096 * 32 * 16 * 16];   // 128 MB  [B,32,16,16]
__device__ float g_h2[4096 * 64 * 8 * 8];     //  64 MB  [B,64,8,8]
__device__ float g_feat[4096 * 128];          //   2 MB  [B,128]

// =============================================================================
// Stage 1: conv(3->32, 3x3 SAME) + bias + BN + ReLU + 2x2 maxpool
// in: x [B,3,32,32]  out: g_h1 [B,32,16,16]
// grid = B, block = 256
// =============================================================================
__global__ __launch_bounds__(256) void conv1_kernel(
    const float* __restrict__ x,
    const float* __restrict__ w,     // [32,3,3,3]
    const float* __restrict__ bias,
    const float* __restrict__ gam,
    const float* __restrict__ bet,
    const float* __restrict__ mean,
    const float* __restrict__ var)
{
    __shared__ float s_in[3][34][35];   // zero-padded (pad=1), col stride 35
    __shared__ float s_w[32 * 27];
    __shared__ float s_scale[32], s_shift[32];

    const int b = blockIdx.x;
    const int tid = threadIdx.x;
    const float* xb = x + (size_t)b * 3 * 32 * 32;

    for (int i = tid; i < 3 * 34 * 34; i += 256) {
        int c = i / (34 * 34);
        int r = (i / 34) % 34;
        int cc = i % 34;
        float v = 0.f;
        if (r >= 1 && r <= 32 && cc >= 1 && cc <= 32)
            v = xb[c * 1024 + (r - 1) * 32 + (cc - 1)];
        s_in[c][r][cc] = v;
    }
    for (int i = tid; i < 32 * 27; i += 256) s_w[i] = w[i];
    if (tid < 32) {
        float inv = gam[tid] * rsqrtf(var[tid] + BN_EPS);
        s_scale[tid] = inv;
        s_shift[tid] = (bias[tid] - mean[tid]) * inv + bet[tid];
    }
    __syncthreads();

    float* ob = g_h1 + (size_t)b * 32 * 256;

    // 1024 work items = 32 oc x 16 pooled-rows x 2 halves; 4 per thread
    for (int rep = 0; rep < 4; rep++) {
        int wk = tid + rep * 256;
        int oc = wk >> 5;
        int rem = wk & 31;
        int py = rem >> 1;
        int half = rem & 1;
        int x0 = half * 16;          // conv-col base (padded col base = x0)
        int r0 = 2 * py;             // padded row base (covers 4 rows)

        float acc0[16], acc1[16];
        #pragma unroll
        for (int i = 0; i < 16; i++) { acc0[i] = 0.f; acc1[i] = 0.f; }

        for (int ic = 0; ic < 3; ic++) {
            float wr[9];
            #pragma unroll
            for (int k = 0; k < 9; k++) wr[k] = s_w[oc * 27 + ic * 9 + k];

            float c0[4], c1[4];
            #pragma unroll
            for (int dy = 0; dy < 4; dy++) {
                c0[dy] = s_in[ic][r0 + dy][x0];
                c1[dy] = s_in[ic][r0 + dy][x0 + 1];
            }
            #pragma unroll
            for (int cx = 0; cx < 16; cx++) {
                float c2[4];
                #pragma unroll
                for (int dy = 0; dy < 4; dy++) c2[dy] = s_in[ic][r0 + dy][x0 + cx + 2];
                acc0[cx] += (wr[0] * c0[0] + wr[1] * c1[0] + wr[2] * c2[0])
                          + (wr[3] * c0[1] + wr[4] * c1[1] + wr[5] * c2[1])
                          + (wr[6] * c0[2] + wr[7] * c1[2] + wr[8] * c2[2]);
                acc1[cx] += (wr[0] * c0[1] + wr[1] * c1[1] + wr[2] * c2[1])
                          + (wr[3] * c0[2] + wr[4] * c1[2] + wr[5] * c2[2])
                          + (wr[6] * c0[3] + wr[7] * c1[3] + wr[8] * c2[3]);
                #pragma unroll
                for (int dy = 0; dy < 4; dy++) { c0[dy] = c1[dy]; c1[dy] = c2[dy]; }
            }
        }
        float sc = s_scale[oc], sh = s_shift[oc];
        #pragma unroll
        for (int px = 0; px < 8; px++) {
            float v00 = fmaxf(fmaf(acc0[2 * px],     sc, sh), 0.f);
            float v01 = fmaxf(fmaf(acc0[2 * px + 1], sc, sh), 0.f);
            float v10 = fmaxf(fmaf(acc1[2 * px],     sc, sh), 0.f);
            float v11 = fmaxf(fmaf(acc1[2 * px + 1], sc, sh), 0.f);
            ob[oc * 256 + py * 16 + half * 8 + px] =
                fmaxf(fmaxf(v00, v01), fmaxf(v10, v11));
        }
    }
}

// =============================================================================
// Stage 2: conv(32->64) + bias + BN + ReLU + pool
// in: g_h1 [B,32,16,16]  out: g_h2 [B,64,8,8]
// grid = B*8 (8 oc-groups of 8), block = 128
// =============================================================================
__global__ __launch_bounds__(128) void conv2_kernel(
    const float* __restrict__ w,     // [64,32,3,3]
    const float* __restrict__ bias,
    const float* __restrict__ gam,
    const float* __restrict__ bet,
    const float* __restrict__ mean,
    const float* __restrict__ var)
{
    __shared__ float s_in[32][16][19]; // cols padded: idx = input col + 1; 0 and 17 are zero
    __shared__ float s_w[2304];        // 8 oc x 32 ic x 9

    const int b = blockIdx.x >> 3;
    const int oc_base = (blockIdx.x & 7) * 8;
    const int tid = threadIdx.x;
    const float* ib = g_h1 + (size_t)b * 8192;

    for (int i = tid; i < 32 * 16 * 19; i += 128) {
        int ic = i / 304;
        int rr = (i / 19) % 16;
        int c = i % 19;
        float v = 0.f;
        if (c >= 1 && c <= 16) v = ib[ic * 256 + rr * 16 + (c - 1)];
        s_in[ic][rr][c] = v;
    }
    for (int i = tid; i < 2304; i += 128) s_w[i] = w[oc_base * 288 + i];
    __syncthreads();

    const int oc_l = tid >> 4;
    const int py = (tid >> 1) & 7;
    const int half = tid & 1;
    const int x0 = half * 8;           // padded col base
    const int rbase = 2 * py - 1;
    const float m0 = (py > 0) ? 1.f : 0.f;
    const float m3 = (py < 7) ? 1.f : 0.f;
    const int r0 = (py > 0) ? rbase : 0;
    const int r1 = rbase + 1, r2 = rbase + 2;
    const int r3 = (py < 7) ? rbase + 3 : 0;

    float acc0[8], acc1[8];
    #pragma unroll
    for (int i = 0; i < 8; i++) { acc0[i] = 0.f; acc1[i] = 0.f; }

    for (int ic = 0; ic < 32; ic++) {
        float wr[9];
        #pragma unroll
        for (int k = 0; k < 9; k++) wr[k] = s_w[oc_l * 288 + ic * 9 + k];

        float c0[4], c1[4];
        c0[0] = m0 * s_in[ic][r0][x0];  c1[0] = m0 * s_in[ic][r0][x0 + 1];
        c0[1] =      s_in[ic][r1][x0];  c1[1] =      s_in[ic][r1][x0 + 1];
        c0[2] =      s_in[ic][r2][x0];  c1[2] =      s_in[ic][r2][x0 + 1];
        c0[3] = m3 * s_in[ic][r3][x0];  c1[3] = m3 * s_in[ic][r3][x0 + 1];
        #pragma unroll
        for (int cx = 0; cx < 8; cx++) {
            float c2[4];
            c2[0] = m0 * s_in[ic][r0][x0 + cx + 2];
            c2[1] =      s_in[ic][r1][x0 + cx + 2];
            c2[2] =      s_in[ic][r2][x0 + cx + 2];
            c2[3] = m3 * s_in[ic][r3][x0 + cx + 2];
            acc0[cx] += (wr[0] * c0[0] + wr[1] * c1[0] + wr[2] * c2[0])
                      + (wr[3] * c0[1] + wr[4] * c1[1] + wr[5] * c2[1])
                      + (wr[6] * c0[2] + wr[7] * c1[2] + wr[8] * c2[2]);
            acc1[cx] += (wr[0] * c0[1] + wr[1] * c1[1] + wr[2] * c2[1])
                      + (wr[3] * c0[2] + wr[4] * c1[2] + wr[5] * c2[2])
                      + (wr[6] * c0[3] + wr[7] * c1[3] + wr[8] * c2[3]);
            #pragma unroll
            for (int dy = 0; dy < 4; dy++) { c0[dy] = c1[dy]; c1[dy] = c2[dy]; }
        }
    }

    const int oc = oc_base + oc_l;
    float inv = gam[oc] * rsqrtf(var[oc] + BN_EPS);
    float sh = (bias[oc] - mean[oc]) * inv + bet[oc];
    float* ob = g_h2 + (size_t)b * 4096 + oc * 64 + py * 8 + half * 4;
    #pragma unroll
    for (int px = 0; px < 4; px++) {
        float v00 = fmaxf(fmaf(acc0[2 * px],     inv, sh), 0.f);
        float v01 = fmaxf(fmaf(acc0[2 * px + 1], inv, sh), 0.f);
        float v10 = fmaxf(fmaf(acc1[2 * px],     inv, sh), 0.f);
        float v11 = fmaxf(fmaf(acc1[2 * px + 1], inv, sh), 0.f);
        ob[px] = fmaxf(fmaxf(v00, v01), fmaxf(v10, v11));
    }
}

// =============================================================================
// Stage 3: conv(64->128) + bias + BN + ReLU + pool + global 4x4 avgpool
// in: g_h2 [B,64,8,8]  out: g_feat [B,128]
// grid = B*16 (16 oc-groups of 8), block = 128 (4 ic-quarters x 8 oc x 4 rows)
// =============================================================================
__global__ __launch_bounds__(128) void conv3_kernel(
    const float* __restrict__ w,     // [128,64,3,3]
    const float* __restrict__ bias,
    const float* __restrict__ gam,
    const float* __restrict__ bet,
    const float* __restrict__ mean,
    const float* __restrict__ var)
{
    __shared__ float s_in[64][8][10];     // col-padded
    __shared__ float s_w[4608];           // 8 oc x 64 ic x 9
    __shared__ float s_part[4][8][4][16]; // [icq][oc][py][2rows x 8cols]
    __shared__ float s_psum[8][4];

    const int b = blockIdx.x >> 4;
    const int oc_base = (blockIdx.x & 15) * 8;
    const int tid = threadIdx.x;
    const float* ib = g_h2 + (size_t)b * 4096;

    for (int i = tid; i < 64 * 8 * 10; i += 128) {
        int ic = i / 80;
        int rr = (i / 10) % 8;
        int c = i % 10;
        float v = 0.f;
        if (c >= 1 && c <= 8) v = ib[ic * 64 + rr * 8 + (c - 1)];
        s_in[ic][rr][c] = v;
    }
    for (int i = tid; i < 4608; i += 128) s_w[i] = w[oc_base * 576 + i];
    __syncthreads();

    const int icq = tid >> 5;
    const int oc_l = (tid >> 2) & 7;
    const int py = tid & 3;
    const int rbase = 2 * py - 1;
    const float m0 = (py > 0) ? 1.f : 0.f;
    const float m3 = (py < 3) ? 1.f : 0.f;
    const int r0 = (py > 0) ? rbase : 0;
    const int r1 = rbase + 1, r2 = rbase + 2;
    const int r3 = (py < 3) ? rbase + 3 : 0;

    float acc0[8], acc1[8];
    #pragma unroll
    for (int i = 0; i < 8; i++) { acc0[i] = 0.f; acc1[i] = 0.f; }

    for (int ici = 0; ici < 16; ici++) {
        int ic = icq * 16 + ici;
        float wr[9];
        #pragma unroll
        for (int k = 0; k < 9; k++) wr[k] = s_w[oc_l * 576 + ic * 9 + k];

        float c0[4], c1[4];
        c0[0] = m0 * s_in[ic][r0][0];  c1[0] = m0 * s_in[ic][r0][1];
        c0[1] =      s_in[ic][r1][0];  c1[1] =      s_in[ic][r1][1];
        c0[2] =      s_in[ic][r2][0];  c1[2] =      s_in[ic][r2][1];
        c0[3] = m3 * s_in[ic][r3][0];  c1[3] = m3 * s_in[ic][r3][1];
        #pragma unroll
        for (int cx = 0; cx < 8; cx++) {
            float c2[4];
            c2[0] = m0 * s_in[ic][r0][cx + 2];
            c2[1] =      s_in[ic][r1][cx + 2];
            c2[2] =      s_in[ic][r2][cx + 2];
            c2[3] = m3 * s_in[ic][r3][cx + 2];
            acc0[cx] += (wr[0] * c0[0] + wr[1] * c1[0] + wr[2] * c2[0])
                      + (wr[3] * c0[1] + wr[4] * c1[1] + wr[5] * c2[1])
                      + (wr[6] * c0[2] + wr[7] * c1[2] + wr[8] * c2[2]);
            acc1[cx] += (wr[0] * c0[1] + wr[1] * c1[1] + wr[2] * c2[1])
                      + (wr[3] * c0[2] + wr[4] * c1[2] + wr[5] * c2[2])
                      + (wr[6] * c0[3] + wr[7] * c1[3] + wr[8] * c2[3]);
            #pragma unroll
            for (int dy = 0; dy < 4; dy++) { c0[dy] = c1[dy]; c1[dy] = c2[dy]; }
        }
    }

    #pragma unroll
    for (int i = 0; i < 8; i++) {
        s_part[icq][oc_l][py][i] = acc0[i];
        s_part[icq][oc_l][py][8 + i] = acc1[i];
    }
    __syncthreads();

    if (icq == 0) {
        const int oc = oc_base + oc_l;
        float inv = gam[oc] * rsqrtf(var[oc] + BN_EPS);
        float sh = (bias[oc] - mean[oc]) * inv + bet[oc];
        float sum = 0.f;
        #pragma unroll
        for (int px = 0; px < 4; px++) {
            float a00 = s_part[0][oc_l][py][2 * px]     + s_part[1][oc_l][py][2 * px]
                      + s_part[2][oc_l][py][2 * px]     + s_part[3][oc_l][py][2 * px];
            float a01 = s_part[0][oc_l][py][2 * px + 1] + s_part[1][oc_l][py][2 * px + 1]
                      + s_part[2][oc_l][py][2 * px + 1] + s_part[3][oc_l][py][2 * px + 1];
            float a10 = s_part[0][oc_l][py][8 + 2 * px]     + s_part[1][oc_l][py][8 + 2 * px]
                      + s_part[2][oc_l][py][8 + 2 * px]     + s_part[3][oc_l][py][8 + 2 * px];
            float a11 = s_part[0][oc_l][py][8 + 2 * px + 1] + s_part[1][oc_l][py][8 + 2 * px + 1]
                      + s_part[2][oc_l][py][8 + 2 * px + 1] + s_part[3][oc_l][py][8 + 2 * px + 1];
            float v00 = fmaxf(fmaf(a00, inv, sh), 0.f);
            float v01 = fmaxf(fmaf(a01, inv, sh), 0.f);
            float v10 = fmaxf(fmaf(a10, inv, sh), 0.f);
            float v11 = fmaxf(fmaf(a11, inv, sh), 0.f);
            sum += fmaxf(fmaxf(v00, v01), fmaxf(v10, v11));
        }
        s_psum[oc_l][py] = sum;
    }
    __syncthreads();

    if (tid < 8) {
        g_feat[(size_t)b * 128 + oc_base + tid] =
            (s_psum[tid][0] + s_psum[tid][1] + s_psum[tid][2] + s_psum[tid][3]) * (1.f / 16.f);
    }
}

// =============================================================================
// Stage 4: gate (top-2 softmax) + top-2 expert MLPs, fused.
// in: g_feat [B,128], out: d_out [B,10]
// grid = B/8, block = 256 (1 warp per sample)
// =============================================================================
__global__ __launch_bounds__(256) void moe_kernel(
    const float* __restrict__ w1,   // [8,128,64]
    const float* __restrict__ b1,   // [8,64]
    const float* __restrict__ w2,   // [8,64,10]
    const float* __restrict__ b2,   // [8,10]
    const float* __restrict__ gw,   // [128,8]
    const float* __restrict__ gb,   // [8]
    float* __restrict__ out, int B)
{
    __shared__ float s_feat[8][128];
    __shared__ float s_h[8][64];
    __shared__ float s_log[8][8];

    const int warp = threadIdx.x >> 5;
    const int lane = threadIdx.x & 31;
    const int s = blockIdx.x * 8 + warp;
    if (s >= B) return;

    for (int i = lane; i < 128; i += 32) s_feat[warp][i] = g_feat[(size_t)s * 128 + i];
    __syncwarp();

    if (lane < 8) {
        float a = gb[lane];
        for (int f = 0; f < 128; f++) a += s_feat[warp][f] * gw[f * 8 + lane];
        s_log[warp][lane] = a;
    }
    __syncwarp();

    // top-2 (computed redundantly in all lanes; matches lax.top_k tie semantics)
    float lg[8];
    #pragma unroll
    for (int e = 0; e < 8; e++) lg[e] = s_log[warp][e];
    int i0 = 0; float v0 = lg[0];
    #pragma unroll
    for (int e = 1; e < 8; e++) if (lg[e] > v0) { v0 = lg[e]; i0 = e; }
    int i1 = -1; float v1 = -3.402823466e38f;
    #pragma unroll
    for (int e = 0; e < 8; e++) if (e != i0 && lg[e] > v1) { v1 = lg[e]; i1 = e; }
    float e1 = expf(v1 - v0);
    float invs = 1.f / (1.f + e1);
    float wts[2] = { invs, e1 * invs };
    int eidx[2] = { i0, i1 };

    float outk = 0.f;
    for (int t = 0; t < 2; t++) {
        const int e = eidx[t];
        const float* w1e = w1 + (size_t)e * 128 * 64;
        float h0 = b1[e * 64 + lane];
        float h1v = b1[e * 64 + lane + 32];
        for (int f = 0; f < 128; f++) {
            float fv = s_feat[warp][f];
            h0  += fv * w1e[f * 64 + lane];
            h1v += fv * w1e[f * 64 + lane + 32];
        }
        s_h[warp][lane] = fmaxf(h0, 0.f);
        s_h[warp][lane + 32] = fmaxf(h1v, 0.f);
        __syncwarp();
        if (lane < 10) {
            const float* w2e = w2 + e * 640;
            float o = b2[e * 10 + lane];
            for (int j = 0; j < 64; j++) o += s_h[warp][j] * w2e[j * 10 + lane];
            outk += wts[t] * o;
        }
        __syncwarp();
    }
    if (lane < 10) out[(size_t)s * 10 + lane] = outk;
}

// =============================================================================
extern "C" void kernel_launch(void* const* d_in, const int* in_sizes, int n_in,
                              void* d_out, int out_size)
{
    const float* x       = (const float*)d_in[0];
    const float* c1w     = (const float*)d_in[1];
    const float* c1b     = (const float*)d_in[2];
    const float* bn1g    = (const float*)d_in[3];
    const float* bn1b    = (const float*)d_in[4];
    const float* bn1m    = (const float*)d_in[5];
    const float* bn1v    = (const float*)d_in[6];
    const float* c2w     = (const float*)d_in[7];
    const float* c2b     = (const float*)d_in[8];
    const float* bn2g    = (const float*)d_in[9];
    const float* bn2b    = (const float*)d_in[10];
    const float* bn2m    = (const float*)d_in[11];
    const float* bn2v    = (const float*)d_in[12];
    const float* c3w     = (const float*)d_in[13];
    const float* c3b     = (const float*)d_in[14];
    const float* bn3g    = (const float*)d_in[15];
    const float* bn3b    = (const float*)d_in[16];
    const float* bn3m    = (const float*)d_in[17];
    const float* bn3v    = (const float*)d_in[18];
    const float* w1      = (const float*)d_in[19];
    const float* b1      = (const float*)d_in[20];
    const float* w2      = (const float*)d_in[21];
    const float* b2      = (const float*)d_in[22];
    const float* gate_w  = (const float*)d_in[23];
    const float* gate_b  = (const float*)d_in[24];

    int B = in_sizes[0] / (3 * 32 * 32);
    if (B > 4096) B = 4096;

    conv1_kernel<<<B, 256>>>(x, c1w, c1b, bn1g, bn1b, bn1m, bn1v);
    conv2_kernel<<<B * 8, 128>>>(c2w, c2b, bn2g, bn2b, bn2m, bn2v);
    conv3_kernel<<<B * 16, 128>>>(c3w, c3b, bn3g, bn3b, bn3m, bn3v);
    moe_kernel<<<(B + 7) / 8, 256>>>(w1, b1, w2, b2, gate_w, gate_b, (float*)d_out, B);
}